// round 11
// baseline (speedup 1.0000x reference)
#include <cuda_runtime.h>

#define B_TOT    131072
#define DIN      128
#define SDIM     64
#define ROWS     128
#define NTHREADS 256
#define PAD      130
#define HALF_LOG2PI 0.9189385332046727f

// kernel1 smem float offsets
#define YS_OFF   0                        // 128*130 = 16640 floats
#define ST2_OFF  0                        // overlay after GEMVs (32*PAD)
#define EPS2_OFF (32*PAD)
#define LP_OFF   (DIN*PAD)                // 16640
#define MISS_BYTE_OFF ((LP_OFF + ROWS)*4) // real-miss bytes: 32 cols
#define SMEM_BYTES (MISS_BYTE_OFF + 32*PAD)  // 71232 B -> 3 CTAs/SM

typedef unsigned long long u64;

// Repacked weights (prep kernel) + logits scratch
__device__ float4 g_Wc2[DIN*16*4];   // [d][fpair][8 f32x2: o0..o6,pad]
__device__ float2 g_Wr2[DIN*32];     // [d][f] (mean_w, logvar_w)
__device__ float  g_Wzt[SDIM*64];    // [d][z]
__device__ float2 g_bc2[16*8];       // cat bias pairs
__device__ float  g_logits[(size_t)B_TOT*224];   // [row][f][7]

__global__ void repack_kernel(const float* __restrict__ Wc,
                              const float* __restrict__ Wr,
                              const float* __restrict__ Wz,
                              const float* __restrict__ bc) {
    int idx = blockIdx.x*blockDim.x + threadIdx.x;
    if (idx < DIN*32) {
        int d = idx >> 5, f = idx & 31;
        g_Wr2[d*32 + f] = make_float2(Wr[(f*DIN + d)*2], Wr[(f*DIN + d)*2 + 1]);
        int dz = idx >> 6, z = idx & 63;
        g_Wzt[dz*64 + z] = Wz[z*SDIM + dz];
    }
    if (idx < DIN*16) {
        int d = idx >> 4, fp = idx & 15;
        const float* s0 = Wc + ((2*fp)*DIN + d)*7;
        const float* s1 = Wc + ((2*fp+1)*DIN + d)*7;
        float4* dst = &g_Wc2[(d*16 + fp)*4];
        dst[0] = make_float4(s0[0], s1[0], s0[1], s1[1]);
        dst[1] = make_float4(s0[2], s1[2], s0[3], s1[3]);
        dst[2] = make_float4(s0[4], s1[4], s0[5], s1[5]);
        dst[3] = make_float4(s0[6], s1[6], 0.0f, 0.0f);
    }
    if (idx < 128) {
        int fp = idx >> 3, o = idx & 7;
        g_bc2[idx] = (o < 7) ? make_float2(bc[(2*fp)*7 + o], bc[(2*fp+1)*7 + o])
                             : make_float2(0.0f, 0.0f);
    }
}

__device__ __forceinline__ u64 pack2(float lo, float hi) {
    u64 r; asm("mov.b64 %0, {%1, %2};" : "=l"(r) : "f"(lo), "f"(hi)); return r;
}
__device__ __forceinline__ float2 unpack2(u64 v) {
    float2 r; asm("mov.b64 {%0, %1}, %2;" : "=f"(r.x), "=f"(r.y) : "l"(v)); return r;
}
__device__ __forceinline__ void fma2(u64 &d, u64 a, u64 b) {
    asm("fma.rn.f32x2 %0, %1, %2, %0;" : "+l"(d) : "l"(a), "l"(b));
}
// load a row-pair and duplicate each into a u64
__device__ __forceinline__ void ld_rowpair(const float* p, u64& Alo, u64& Ahi) {
    float2 f = *(const float2*)p;    // LDS.64
    Alo = pack2(f.x, f.x);
    Ahi = pack2(f.y, f.y);
}

// t = -log(u), accurate near u->1
__device__ __forceinline__ float neg_log_u(float u) {
    float v = 1.0f - u;
    if (v < 0.0078125f)
        return v*(1.0f + v*(0.5f + v*(1.0f/3.0f)));
    return -__logf(u);
}

// =================== kernel 1: GEMVs + real epilogue =======================
__global__ __launch_bounds__(NTHREADS, 3)
void hivae_gemv_kernel(const float* __restrict__ y,   const float* __restrict__ s,
                       const float* __restrict__ st,  const float* __restrict__ bz,
                       const float* __restrict__ br,  const float* __restrict__ eps,
                       const int* __restrict__ miss,  float* __restrict__ out)
{
    extern __shared__ float sm[];
    char* smc = (char*)sm + MISS_BYTE_OFF;
    const int tid = threadIdx.x;
    const int rb  = blockIdx.x * ROWS;
    const int warp = tid >> 5, lane = tid & 31;
    const long B64 = (long)B_TOT*64;

    int R[4];
    R[0] = 2*lane; R[1] = 2*lane + 1; R[2] = 64 + 2*lane; R[3] = 64 + 2*lane + 1;

    // ---------------- stage YS (transposed) + real-miss bytes ---------------
    for (int idx = tid; idx < ROWS*DIN; idx += NTHREADS) {
        int row = idx >> 7, c = idx & 127;
        float v = (c < 64) ? y[(rb+row)*64 + c] : s[(rb+row)*64 + (c-64)];
        sm[YS_OFF + c*PAD + row] = v;
    }
    for (int idx = tid; idx < ROWS*32; idx += NTHREADS) {
        int row = idx >> 5, c = idx & 31;
        smc[c*PAD + row] = (char)miss[(rb+row)*64 + c];
    }
    if (tid < ROWS) sm[LP_OFF + tid] = 0.0f;
    __syncthreads();

    float lp_r[4] = {0.f, 0.f, 0.f, 0.f};

    // ========== categorical GEMV: 4 rows per weight stream -> logits =======
    #pragma unroll 1
    for (int jj = 0; jj < 2; jj++) {
        const int fp = jj*8 + warp;          // features 2fp, 2fp+1
        u64 acc[4][7];
        {
            const float2* bp = &g_bc2[fp*8];
            #pragma unroll
            for (int o = 0; o < 7; o++) {
                float2 b = bp[o];
                u64 v = pack2(b.x, b.y);
                acc[0][o] = v; acc[1][o] = v; acc[2][o] = v; acc[3][o] = v;
            }
        }
        #pragma unroll 4
        for (int d = 0; d < DIN; d++) {
            const ulonglong2* wp = (const ulonglong2*)&g_Wc2[(d*16 + fp)*4];
            ulonglong2 w0 = wp[0], w1 = wp[1], w2 = wp[2];
            u64 w6 = *(const u64*)(wp + 3);
            u64 A[4];
            ld_rowpair(&sm[YS_OFF + d*PAD + 2*lane],      A[0], A[1]);
            ld_rowpair(&sm[YS_OFF + d*PAD + 64 + 2*lane], A[2], A[3]);
            #pragma unroll
            for (int i = 0; i < 4; i++) {
                fma2(acc[i][0], A[i], w0.x); fma2(acc[i][1], A[i], w0.y);
                fma2(acc[i][2], A[i], w1.x); fma2(acc[i][3], A[i], w1.y);
                fma2(acc[i][4], A[i], w2.x); fma2(acc[i][5], A[i], w2.y);
                fma2(acc[i][6], A[i], w6);
            }
        }
        // store logits: [row][f][7], features 2fp/2fp+1 at fp*14
        #pragma unroll
        for (int i = 0; i < 4; i++) {
            const long grow = rb + R[i];
            float2* dst = (float2*)(g_logits + grow*224 + fp*14);
            float lg0[7], lg1[7];
            #pragma unroll
            for (int o = 0; o < 7; o++) {
                float2 v = unpack2(acc[i][o]); lg0[o] = v.x; lg1[o] = v.y;
            }
            dst[0] = make_float2(lg0[0], lg0[1]);
            dst[1] = make_float2(lg0[2], lg0[3]);
            dst[2] = make_float2(lg0[4], lg0[5]);
            dst[3] = make_float2(lg0[6], lg1[0]);
            dst[4] = make_float2(lg1[1], lg1[2]);
            dst[5] = make_float2(lg1[3], lg1[4]);
            dst[6] = make_float2(lg1[5], lg1[6]);
        }
    }

    // ========== mean_pz: 8 z-outputs x 4 rows ==============================
    {
        const int zb = warp*8;
        u64 az[4][4];
        {
            float4 b0 = *(const float4*)&bz[zb];
            float4 b1 = *(const float4*)&bz[zb + 4];
            u64 v0 = pack2(b0.x, b0.y), v1 = pack2(b0.z, b0.w);
            u64 v2 = pack2(b1.x, b1.y), v3 = pack2(b1.z, b1.w);
            #pragma unroll
            for (int i = 0; i < 4; i++) {
                az[i][0] = v0; az[i][1] = v1; az[i][2] = v2; az[i][3] = v3;
            }
        }
        #pragma unroll 4
        for (int d = 0; d < SDIM; d++) {
            ulonglong2 w0 = *(const ulonglong2*)&g_Wzt[d*64 + zb];
            ulonglong2 w1 = *(const ulonglong2*)&g_Wzt[d*64 + zb + 4];
            u64 A[4];
            ld_rowpair(&sm[YS_OFF + (64+d)*PAD + 2*lane],      A[0], A[1]);
            ld_rowpair(&sm[YS_OFF + (64+d)*PAD + 64 + 2*lane], A[2], A[3]);
            #pragma unroll
            for (int i = 0; i < 4; i++) {
                fma2(az[i][0], A[i], w0.x); fma2(az[i][1], A[i], w0.y);
                fma2(az[i][2], A[i], w1.x); fma2(az[i][3], A[i], w1.y);
            }
        }
        #pragma unroll
        for (int i = 0; i < 4; i++) {
            const long grow = rb + R[i];
            float2 p0 = unpack2(az[i][0]), p1 = unpack2(az[i][1]);
            float2 p2 = unpack2(az[i][2]), p3 = unpack2(az[i][3]);
            *(float4*)&out[B64 + grow*64 + zb]     = make_float4(p0.x, p0.y, p1.x, p1.y);
            *(float4*)&out[B64 + grow*64 + zb + 4] = make_float4(p2.x, p2.y, p3.x, p3.y);
        }
    }

    // ========== real GEMV: 4 features x 4 rows =============================
    u64 ar[4][4];
    {
        const int f0 = warp*4;
        float4 b0 = *(const float4*)&br[f0*2];
        float4 b1 = *(const float4*)&br[f0*2 + 4];
        u64 v0 = pack2(b0.x, b0.y), v1 = pack2(b0.z, b0.w);
        u64 v2 = pack2(b1.x, b1.y), v3 = pack2(b1.z, b1.w);
        #pragma unroll
        for (int i = 0; i < 4; i++) {
            ar[i][0] = v0; ar[i][1] = v1; ar[i][2] = v2; ar[i][3] = v3;
        }
        #pragma unroll 4
        for (int d = 0; d < DIN; d++) {
            ulonglong2 wA = *(const ulonglong2*)&g_Wr2[d*32 + f0];
            ulonglong2 wB = *(const ulonglong2*)&g_Wr2[d*32 + f0 + 2];
            u64 A[4];
            ld_rowpair(&sm[YS_OFF + d*PAD + 2*lane],      A[0], A[1]);
            ld_rowpair(&sm[YS_OFF + d*PAD + 64 + 2*lane], A[2], A[3]);
            #pragma unroll
            for (int i = 0; i < 4; i++) {
                fma2(ar[i][0], A[i], wA.x); fma2(ar[i][1], A[i], wA.y);
                fma2(ar[i][2], A[i], wB.x); fma2(ar[i][3], A[i], wB.y);
            }
        }
    }

    // ---- overlay st/eps into the YS region ---------------------------------
    __syncthreads();
    for (int idx = tid; idx < ROWS*32; idx += NTHREADS) {
        int row = idx >> 5, c = idx & 31;
        sm[ST2_OFF  + c*PAD + row] = st[(rb+row)*288 + c];
        sm[EPS2_OFF + c*PAD + row] = eps[(rb+row)*32 + c];
    }
    __syncthreads();

    // ========== real epilogue ==============================================
    {
        const int f0 = warp*4;
        #pragma unroll 1
        for (int i = 0; i < 4; i++) {
            const int r = R[i];
            const long grow = rb + r;
            float samp[4];
            #pragma unroll
            for (int qf = 0; qf < 4; qf++) {
                const int f = f0 + qf;
                float2 mv = unpack2(ar[i][qf]);
                float mu = mv.x;
                float lv = fminf(fmaxf(mv.y, -10.0f), 10.0f);
                float x  = sm[ST2_OFF + f*PAD + r];
                float mi = (float)smc[f*PAD + r];
                float dmu = x - mu;
                lp_r[i] += (-0.5f*dmu*dmu*__expf(-lv) - 0.5f*lv - HALF_LOG2PI) * mi;
                float sd = fmaxf(__expf(0.5f*lv), 1e-6f);
                samp[qf] = mu + sd * sm[EPS2_OFF + f*PAD + r];
            }
            *(float4*)&out[grow*64 + f0] = make_float4(samp[0], samp[1], samp[2], samp[3]);
        }
    }

    // -------- real log-p reduction + zeros ----------------------------------
    #pragma unroll
    for (int i = 0; i < 4; i++)
        atomicAdd(&sm[LP_OFF + R[i]], lp_r[i]);

    {
        const float4 z4 = make_float4(0.f,0.f,0.f,0.f);
        for (int idx = tid; idx < ROWS*16; idx += NTHREADS) {
            int row = idx >> 4, c = (idx & 15)*4;
            *(float4*)&out[2*B64 + (long)(rb+row)*64 + c] = z4;
        }
    }

    __syncthreads();
    if (tid < ROWS) out[3*B64 + rb + tid] = sm[LP_OFF + tid];   // real part
}

// =================== kernel 2: cat epilogue (streaming) ====================
// 1 warp = 1 row, 1 lane = 1 feature. All loads coalesced.
__global__ __launch_bounds__(256)
void cat_epi_kernel(const float* __restrict__ st, const float* __restrict__ gum,
                    const int* __restrict__ miss, float* __restrict__ out)
{
    const long B64 = (long)B_TOT*64;
    const long row = (long)blockIdx.x*8 + (threadIdx.x >> 5);
    const int  f   = threadIdx.x & 31;

    // logits
    const float* lg = g_logits + row*224 + f*7;
    float lpi[8];
    lpi[0] = 0.0f;
    #pragma unroll
    for (int k = 1; k < 8; k++) lpi[k] = lg[k-1];

    // data + gumbel + miss (coalesced)
    const float4* dc = (const float4*)(st + row*288 + 32 + f*8);
    float4 D0 = dc[0], D1 = dc[1];
    const float4* gu = (const float4*)(gum + row*256 + f*8);
    float4 G0 = gu[0], G1 = gu[1];
    float missf = (float)miss[row*64 + 32 + f];

    float m = lpi[0];
    #pragma unroll
    for (int k = 1; k < 8; k++) m = fmaxf(m, lpi[k]);
    float e[8], se = 0.0f;
    #pragma unroll
    for (int k = 0; k < 8; k++) { e[k] = __expf(lpi[k] - m); se += e[k]; }
    float lse = m + __logf(se);

    float lp = D0.x*(lpi[0]-lse) + D0.y*(lpi[1]-lse) + D0.z*(lpi[2]-lse) + D0.w*(lpi[3]-lse)
             + D1.x*(lpi[4]-lse) + D1.y*(lpi[5]-lse) + D1.z*(lpi[6]-lse) + D1.w*(lpi[7]-lse);
    lp *= missf;

    float uv[8] = {G0.x,G0.y,G0.z,G0.w,G1.x,G1.y,G1.z,G1.w};
    float t[8];
    #pragma unroll
    for (int k = 0; k < 8; k++) {
        float u = fminf(fmaxf(uv[k], 1e-6f), 1.0f - 1e-6f);
        t[k] = neg_log_u(u);
    }
    float be = e[0], bt = t[0]; int bi = 0;
    #pragma unroll
    for (int k = 1; k < 8; k++) {
        if (e[k]*bt > be*t[k]) { be = e[k]; bt = t[k]; bi = k; }
    }
    out[row*64 + 32 + f] = (float)bi;      // samples_cat, coalesced

    // warp-reduce cat log-p, add to real part written by kernel 1
    #pragma unroll
    for (int off = 16; off > 0; off >>= 1)
        lp += __shfl_xor_sync(0xFFFFFFFFu, lp, off);
    if (f == 0) out[3*B64 + row] += lp;
}

extern "C" void kernel_launch(void* const* d_in, const int* in_sizes, int n_in,
                              void* d_out, int out_size)
{
    const float* y    = (const float*)d_in[0];
    const float* s    = (const float*)d_in[1];
    const float* st   = (const float*)d_in[2];
    const float* Wz   = (const float*)d_in[3];
    const float* bz   = (const float*)d_in[4];
    const float* Wr   = (const float*)d_in[5];
    const float* br   = (const float*)d_in[6];
    const float* Wc   = (const float*)d_in[7];
    const float* bc   = (const float*)d_in[8];
    const float* eps  = (const float*)d_in[9];
    const float* gum  = (const float*)d_in[10];
    const int*   miss = (const int*)d_in[11];
    float* out = (float*)d_out;

    cudaFuncSetAttribute(hivae_gemv_kernel,
                         cudaFuncAttributeMaxDynamicSharedMemorySize, SMEM_BYTES);
    repack_kernel<<<16, 256>>>(Wc, Wr, Wz, bc);
    hivae_gemv_kernel<<<B_TOT/ROWS, NTHREADS, SMEM_BYTES>>>(
        y, s, st, bz, br, eps, miss, out);
    cat_epi_kernel<<<B_TOT/8, 256>>>(st, gum, miss, out);
}

// round 12
// speedup vs baseline: 1.0226x; 1.0226x over previous
#include <cuda_runtime.h>

#define B_TOT    131072
#define DIN      128
#define SDIM     64
#define ROWS     64
#define NTHREADS 256
#define PAD      66
#define HALF_LOG2PI 0.9189385332046727f

// smem float offsets
#define YS_OFF   0                        // 128*66 = 8448 floats
#define ST2_OFF  0                        // overlay after GEMVs
#define EPS2_OFF (32*PAD)
#define LP_OFF   (DIN*PAD)                // 8448
#define MISS_BYTE_OFF ((LP_OFF + ROWS)*4) // 34048
#define SMEM_BYTES (MISS_BYTE_OFF + 64*PAD)  // 38272 B -> 3 CTAs (regs), L1D ~100KB

typedef unsigned long long u64;

// Repacked weights (prep kernel)
__device__ float4 g_Wc2[DIN*16*4];   // [d][fpair][8 f32x2: o0..o6,pad]
__device__ float2 g_Wr2[DIN*32];     // [d][f] (mean_w, logvar_w)
__device__ float  g_Wzt[SDIM*64];    // [d][z]
__device__ float2 g_bc2[16*8];       // cat bias pairs

__global__ void repack_kernel(const float* __restrict__ Wc,
                              const float* __restrict__ Wr,
                              const float* __restrict__ Wz,
                              const float* __restrict__ bc) {
    int idx = blockIdx.x*blockDim.x + threadIdx.x;
    if (idx < DIN*32) {
        int d = idx >> 5, f = idx & 31;
        g_Wr2[d*32 + f] = make_float2(Wr[(f*DIN + d)*2], Wr[(f*DIN + d)*2 + 1]);
        int dz = idx >> 6, z = idx & 63;
        g_Wzt[dz*64 + z] = Wz[z*SDIM + dz];
    }
    if (idx < DIN*16) {
        int d = idx >> 4, fp = idx & 15;
        const float* s0 = Wc + ((2*fp)*DIN + d)*7;
        const float* s1 = Wc + ((2*fp+1)*DIN + d)*7;
        float4* dst = &g_Wc2[(d*16 + fp)*4];
        dst[0] = make_float4(s0[0], s1[0], s0[1], s1[1]);
        dst[1] = make_float4(s0[2], s1[2], s0[3], s1[3]);
        dst[2] = make_float4(s0[4], s1[4], s0[5], s1[5]);
        dst[3] = make_float4(s0[6], s1[6], 0.0f, 0.0f);
    }
    if (idx < 128) {
        int fp = idx >> 3, o = idx & 7;
        g_bc2[idx] = (o < 7) ? make_float2(bc[(2*fp)*7 + o], bc[(2*fp+1)*7 + o])
                             : make_float2(0.0f, 0.0f);
    }
}

__device__ __forceinline__ u64 pack2(float lo, float hi) {
    u64 r; asm("mov.b64 %0, {%1, %2};" : "=l"(r) : "f"(lo), "f"(hi)); return r;
}
__device__ __forceinline__ float2 unpack2(u64 v) {
    float2 r; asm("mov.b64 {%0, %1}, %2;" : "=f"(r.x), "=f"(r.y) : "l"(v)); return r;
}
__device__ __forceinline__ void fma2(u64 &d, u64 a, u64 b) {
    asm("fma.rn.f32x2 %0, %1, %2, %0;" : "+l"(d) : "l"(a), "l"(b));
}
// load a row-pair and duplicate each into a u64 (broadcast across half-warps)
__device__ __forceinline__ void ld_rowpair(const float* p, u64& Alo, u64& Ahi) {
    float2 f = *(const float2*)p;    // LDS.64
    Alo = pack2(f.x, f.x);
    Ahi = pack2(f.y, f.y);
}

// t = -log(u), accurate near u->1
__device__ __forceinline__ float neg_log_u(float u) {
    float v = 1.0f - u;
    if (v < 0.0078125f)
        return v*(1.0f + v*(0.5f + v*(1.0f/3.0f)));
    return -__logf(u);
}

// epilogue for one (row, feature): 7 logits (l0 = 0 implicit)
__device__ __forceinline__ void cat_epilogue(
    const float* __restrict__ lg,
    float4 G0, float4 G1, float4 D0, float4 D1,
    float missf, float& lp_out, float& samp_out)
{
    float lpi[8];
    lpi[0] = 0.0f;
    #pragma unroll
    for (int k = 1; k < 8; k++) lpi[k] = lg[k-1];
    float m = lpi[0];
    #pragma unroll
    for (int k = 1; k < 8; k++) m = fmaxf(m, lpi[k]);
    float e[8], se = 0.0f;
    #pragma unroll
    for (int k = 0; k < 8; k++) { e[k] = __expf(lpi[k] - m); se += e[k]; }
    float lse = m + __logf(se);

    float lp = D0.x*(lpi[0]-lse) + D0.y*(lpi[1]-lse) + D0.z*(lpi[2]-lse) + D0.w*(lpi[3]-lse)
             + D1.x*(lpi[4]-lse) + D1.y*(lpi[5]-lse) + D1.z*(lpi[6]-lse) + D1.w*(lpi[7]-lse);
    lp_out += lp * missf;

    float uv[8] = {G0.x,G0.y,G0.z,G0.w,G1.x,G1.y,G1.z,G1.w};
    float t[8];
    #pragma unroll
    for (int k = 0; k < 8; k++) {
        float u = fminf(fmaxf(uv[k], 1e-6f), 1.0f - 1e-6f);
        t[k] = neg_log_u(u);
    }
    float be = e[0], bt = t[0]; int bi = 0;
    #pragma unroll
    for (int k = 1; k < 8; k++) {
        if (e[k]*bt > be*t[k]) { be = e[k]; bt = t[k]; bi = k; }
    }
    samp_out = (float)bi;
}

__global__ __launch_bounds__(NTHREADS, 3)
void hivae_kernel(const float* __restrict__ y,   const float* __restrict__ s,
                  const float* __restrict__ st,  const float* __restrict__ bz,
                  const float* __restrict__ br,  const float* __restrict__ eps,
                  const float* __restrict__ gum, const int* __restrict__ miss,
                  float* __restrict__ out)
{
    extern __shared__ float sm[];
    char* smc = (char*)sm + MISS_BYTE_OFF;
    const int tid = threadIdx.x;
    const int rb  = blockIdx.x * ROWS;
    const int warp = tid >> 5, lane = tid & 31;
    const int q = lane & 15, h = lane >> 4;   // half-warp split
    const int fp  = warp + 8*h;               // cat feature pair 0..15
    const long B64 = (long)B_TOT*64;

    int R[4];
    R[0] = 2*q; R[1] = 2*q + 1; R[2] = 32 + 2*q; R[3] = 32 + 2*q + 1;

    // ---------------- stage YS (transposed) + miss bytes --------------------
    for (int idx = tid; idx < ROWS*DIN; idx += NTHREADS) {
        int row = idx >> 7, c = idx & 127;
        float v = (c < 64) ? y[(rb+row)*64 + c] : s[(rb+row)*64 + (c-64)];
        sm[YS_OFF + c*PAD + row] = v;
    }
    for (int idx = tid; idx < ROWS*64; idx += NTHREADS) {
        int row = idx >> 6, c = idx & 63;
        smc[c*PAD + row] = (char)miss[(rb+row)*64 + c];
    }
    if (tid < ROWS) sm[LP_OFF + tid] = 0.0f;
    __syncthreads();

    float lp_r[4] = {0.f, 0.f, 0.f, 0.f};

    // ========== categorical: ONE pass, 16 fp via half-warp split ===========
    {
        u64 acc[4][7];
        {
            const float2* bp = &g_bc2[fp*8];
            #pragma unroll
            for (int o = 0; o < 7; o++) {
                float2 b = bp[o];
                u64 v = pack2(b.x, b.y);
                acc[0][o] = v; acc[1][o] = v; acc[2][o] = v; acc[3][o] = v;
            }
        }
        #pragma unroll 4
        for (int d = 0; d < DIN; d++) {
            const ulonglong2* wp = (const ulonglong2*)&g_Wc2[(d*16 + fp)*4];
            ulonglong2 w0 = wp[0], w1 = wp[1], w2 = wp[2];
            u64 w6 = *(const u64*)(wp + 3);
            u64 A[4];
            ld_rowpair(&sm[YS_OFF + d*PAD + 2*q],      A[0], A[1]);
            ld_rowpair(&sm[YS_OFF + d*PAD + 32 + 2*q], A[2], A[3]);
            #pragma unroll
            for (int i = 0; i < 4; i++) {
                fma2(acc[i][0], A[i], w0.x); fma2(acc[i][1], A[i], w0.y);
                fma2(acc[i][2], A[i], w1.x); fma2(acc[i][3], A[i], w1.y);
                fma2(acc[i][4], A[i], w2.x); fma2(acc[i][5], A[i], w2.y);
                fma2(acc[i][6], A[i], w6);
            }
        }
        // epilogue, one row at a time
        #pragma unroll 1
        for (int i = 0; i < 4; i++) {
            const int r = R[i];
            const long grow = rb + r;
            const float4* gup = (const float4*)(gum + grow*256 + fp*16);
            const float4* dcp = (const float4*)(st + grow*288 + 32 + fp*16);
            float4 G0 = gup[0], G1 = gup[1], G2 = gup[2], G3 = gup[3];
            float4 D0 = dcp[0], D1 = dcp[1], D2 = dcp[2], D3 = dcp[3];
            float lg0[7], lg1[7];
            #pragma unroll
            for (int o = 0; o < 7; o++) {
                float2 v = unpack2(acc[i][o]); lg0[o] = v.x; lg1[o] = v.y;
            }
            float s0, s1;
            cat_epilogue(lg0, G0, G1, D0, D1,
                         (float)smc[(32+2*fp)*PAD + r], lp_r[i], s0);
            cat_epilogue(lg1, G2, G3, D2, D3,
                         (float)smc[(33+2*fp)*PAD + r], lp_r[i], s1);
            *(float2*)&out[grow*64 + 32 + 2*fp] = make_float2(s0, s1);
        }
    }

    // ========== mean_pz: 4 z-outputs x 4 rows (half-warp split) ============
    {
        const int zb = warp*8 + h*4;
        u64 az[4][2];
        {
            float4 b0 = *(const float4*)&bz[zb];
            u64 v0 = pack2(b0.x, b0.y), v1 = pack2(b0.z, b0.w);
            #pragma unroll
            for (int i = 0; i < 4; i++) { az[i][0] = v0; az[i][1] = v1; }
        }
        #pragma unroll 4
        for (int d = 0; d < SDIM; d++) {
            ulonglong2 w0 = *(const ulonglong2*)&g_Wzt[d*64 + zb];
            u64 A[4];
            ld_rowpair(&sm[YS_OFF + (64+d)*PAD + 2*q],      A[0], A[1]);
            ld_rowpair(&sm[YS_OFF + (64+d)*PAD + 32 + 2*q], A[2], A[3]);
            #pragma unroll
            for (int i = 0; i < 4; i++) {
                fma2(az[i][0], A[i], w0.x); fma2(az[i][1], A[i], w0.y);
            }
        }
        #pragma unroll
        for (int i = 0; i < 4; i++) {
            const long grow = rb + R[i];
            float2 p0 = unpack2(az[i][0]), p1 = unpack2(az[i][1]);
            *(float4*)&out[B64 + grow*64 + zb] = make_float4(p0.x, p0.y, p1.x, p1.y);
        }
    }

    // ========== real GEMV: 2 features x 4 rows (half-warp split) ===========
    u64 ar[4][2];   // [row][feature], (mean, logvar) packed
    const int f0r = warp*4 + h*2;
    {
        float4 b0 = *(const float4*)&br[f0r*2];
        u64 v0 = pack2(b0.x, b0.y), v1 = pack2(b0.z, b0.w);
        #pragma unroll
        for (int i = 0; i < 4; i++) { ar[i][0] = v0; ar[i][1] = v1; }
        #pragma unroll 4
        for (int d = 0; d < DIN; d++) {
            ulonglong2 wA = *(const ulonglong2*)&g_Wr2[d*32 + f0r];
            u64 A[4];
            ld_rowpair(&sm[YS_OFF + d*PAD + 2*q],      A[0], A[1]);
            ld_rowpair(&sm[YS_OFF + d*PAD + 32 + 2*q], A[2], A[3]);
            #pragma unroll
            for (int i = 0; i < 4; i++) {
                fma2(ar[i][0], A[i], wA.x); fma2(ar[i][1], A[i], wA.y);
            }
        }
    }

    // ---- all YS reads done: overlay st/eps into the YS region -------------
    __syncthreads();
    for (int idx = tid; idx < ROWS*32; idx += NTHREADS) {
        int row = idx >> 5, c = idx & 31;
        sm[ST2_OFF  + c*PAD + row] = st[(rb+row)*288 + c];
        sm[EPS2_OFF + c*PAD + row] = eps[(rb+row)*32 + c];
    }
    __syncthreads();

    // ========== real epilogue ==============================================
    {
        #pragma unroll 1
        for (int i = 0; i < 4; i++) {
            const int r = R[i];
            const long grow = rb + r;
            float samp[2];
            #pragma unroll
            for (int qf = 0; qf < 2; qf++) {
                const int f = f0r + qf;
                float2 mv = unpack2(ar[i][qf]);
                float mu = mv.x;
                float lv = fminf(fmaxf(mv.y, -10.0f), 10.0f);
                float x  = sm[ST2_OFF + f*PAD + r];
                float mi = (float)smc[f*PAD + r];
                float dmu = x - mu;
                lp_r[i] += (-0.5f*dmu*dmu*__expf(-lv) - 0.5f*lv - HALF_LOG2PI) * mi;
                float sd = fmaxf(__expf(0.5f*lv), 1e-6f);
                samp[qf] = mu + sd * sm[EPS2_OFF + f*PAD + r];
            }
            *(float2*)&out[grow*64 + f0r] = make_float2(samp[0], samp[1]);
        }
    }

    // -------- log-p reduction + zeros ---------------------------------------
    #pragma unroll
    for (int i = 0; i < 4; i++)
        atomicAdd(&sm[LP_OFF + R[i]], lp_r[i]);

    {
        const float4 z4 = make_float4(0.f,0.f,0.f,0.f);
        for (int idx = tid; idx < ROWS*16; idx += NTHREADS) {
            int row = idx >> 4, c = (idx & 15)*4;
            *(float4*)&out[2*B64 + (long)(rb+row)*64 + c] = z4;
        }
    }

    __syncthreads();
    if (tid < ROWS) out[3*B64 + rb + tid] = sm[LP_OFF + tid];
}

extern "C" void kernel_launch(void* const* d_in, const int* in_sizes, int n_in,
                              void* d_out, int out_size)
{
    const float* y    = (const float*)d_in[0];
    const float* s    = (const float*)d_in[1];
    const float* st   = (const float*)d_in[2];
    const float* Wz   = (const float*)d_in[3];
    const float* bz   = (const float*)d_in[4];
    const float* Wr   = (const float*)d_in[5];
    const float* br   = (const float*)d_in[6];
    const float* Wc   = (const float*)d_in[7];
    const float* bc   = (const float*)d_in[8];
    const float* eps  = (const float*)d_in[9];
    const float* gum  = (const float*)d_in[10];
    const int*   miss = (const int*)d_in[11];
    float* out = (float*)d_out;

    cudaFuncSetAttribute(hivae_kernel,
                         cudaFuncAttributeMaxDynamicSharedMemorySize, SMEM_BYTES);
    repack_kernel<<<16, 256>>>(Wc, Wr, Wz, bc);
    hivae_kernel<<<B_TOT/ROWS, NTHREADS, SMEM_BYTES>>>(
        y, s, st, bz, br, eps, gum, miss, out);
}

// round 14
// speedup vs baseline: 1.6575x; 1.6208x over previous
#include <cuda_runtime.h>
#include <cstdint>

#define B_TOT    131072
#define DIN      128
#define SDIM     64
#define ROWS     128
#define NTHREADS 256
#define PAD      130
#define HALF_LOG2PI 0.9189385332046727f

// smem float offsets
#define YS_OFF   0                        // 128*130 = 16640 floats
#define ST2_OFF  0                        // overlay after GEMVs
#define EPS2_OFF (32*PAD)
#define WBUF_OFF 16640                    // 2 x 4096 floats (16KB each)
#define LP_OFF   24832                    // 128 floats
#define MISS_BYTE_OFF ((LP_OFF + 128)*4)  // 99840
#define SMEM_BYTES (MISS_BYTE_OFF + 64*PAD)  // 108160 B -> 2 CTAs/SM

typedef unsigned long long u64;
typedef unsigned int u32;

// Repacked weights (prep kernel)
__device__ float4 g_Wc2[DIN*16*4];   // [d][fpair][8 f32x2: o0..o6,pad]
__device__ float2 g_Wr2[DIN*32];     // [d][f] (mean_w, logvar_w)
__device__ float  g_Wzt[SDIM*64];    // [d][z]
__device__ float2 g_bc2[16*8];       // cat bias pairs

__global__ void repack_kernel(const float* __restrict__ Wc,
                              const float* __restrict__ Wr,
                              const float* __restrict__ Wz,
                              const float* __restrict__ bc) {
    int idx = blockIdx.x*blockDim.x + threadIdx.x;
    if (idx < DIN*32) {
        int d = idx >> 5, f = idx & 31;
        g_Wr2[d*32 + f] = make_float2(Wr[(f*DIN + d)*2], Wr[(f*DIN + d)*2 + 1]);
        int dz = idx >> 6, z = idx & 63;
        g_Wzt[dz*64 + z] = Wz[z*SDIM + dz];
    }
    if (idx < DIN*16) {
        int d = idx >> 4, fp = idx & 15;
        const float* s0 = Wc + ((2*fp)*DIN + d)*7;
        const float* s1 = Wc + ((2*fp+1)*DIN + d)*7;
        float4* dst = &g_Wc2[(d*16 + fp)*4];
        dst[0] = make_float4(s0[0], s1[0], s0[1], s1[1]);
        dst[1] = make_float4(s0[2], s1[2], s0[3], s1[3]);
        dst[2] = make_float4(s0[4], s1[4], s0[5], s1[5]);
        dst[3] = make_float4(s0[6], s1[6], 0.0f, 0.0f);
    }
    if (idx < 128) {
        int fp = idx >> 3, o = idx & 7;
        g_bc2[idx] = (o < 7) ? make_float2(bc[(2*fp)*7 + o], bc[(2*fp+1)*7 + o])
                             : make_float2(0.0f, 0.0f);
    }
}

__device__ __forceinline__ u64 pack2(float lo, float hi) {
    u64 r; asm("mov.b64 %0, {%1, %2};" : "=l"(r) : "f"(lo), "f"(hi)); return r;
}
__device__ __forceinline__ float2 unpack2(u64 v) {
    float2 r; asm("mov.b64 {%0, %1}, %2;" : "=f"(r.x), "=f"(r.y) : "l"(v)); return r;
}
__device__ __forceinline__ void fma2(u64 &d, u64 a, u64 b) {
    asm("fma.rn.f32x2 %0, %1, %2, %0;" : "+l"(d) : "l"(a), "l"(b));
}
__device__ __forceinline__ void ld_rowpair(const float* p, u64& Alo, u64& Ahi) {
    float2 f = *(const float2*)p;    // LDS.64
    Alo = pack2(f.x, f.x);
    Ahi = pack2(f.y, f.y);
}
__device__ __forceinline__ void cp16(u32 saddr, const void* gaddr) {
    asm volatile("cp.async.cg.shared.global [%0], [%1], 16;" :: "r"(saddr), "l"(gaddr));
}

// Chunk schedule: g=0..7 cat (jj=g>>2, c=g&3: 32 d x 8 fp), g=8 pz (16KB),
// g=9..10 real (2 x 16KB). Always commits a group (possibly empty).
__device__ __forceinline__ void issue_chunk(int g, float* sm, int tid) {
    if (g <= 10) {
        u32 sb = (u32)__cvta_generic_to_shared(sm + WBUF_OFF + (g&1)*4096);
        if (g < 8) {
            int jj = (g >> 2) & 1, c = g & 3;
            #pragma unroll
            for (int k = 0; k < 4; k++) {
                int e = k*256 + tid;
                int dd = e >> 5, rem = e & 31;
                cp16(sb + e*16, g_Wc2 + (c*32+dd)*64 + jj*32 + rem);
            }
        } else if (g == 8) {
            const float4* src = (const float4*)g_Wzt;
            #pragma unroll
            for (int k = 0; k < 4; k++) { int e = k*256+tid; cp16(sb + e*16, src+e); }
        } else {
            const float4* src = (const float4*)g_Wr2 + (g-9)*1024;
            #pragma unroll
            for (int k = 0; k < 4; k++) { int e = k*256+tid; cp16(sb + e*16, src+e); }
        }
    }
    asm volatile("cp.async.commit_group;");
}
__device__ __forceinline__ void wait_prev() {
    asm volatile("cp.async.wait_group 1;");
}

// t = -log(u), accurate near u->1
__device__ __forceinline__ float neg_log_u(float u) {
    float v = 1.0f - u;
    if (v < 0.0078125f)
        return v*(1.0f + v*(0.5f + v*(1.0f/3.0f)));
    return -__logf(u);
}

// epilogue for one (row, feature): 7 logits (l0 = 0 implicit)
__device__ __forceinline__ void cat_epilogue(
    const float* __restrict__ lg,
    float4 G0, float4 G1, float4 D0, float4 D1,
    float missf, float& lp_out, float& samp_out)
{
    float lpi[8];
    lpi[0] = 0.0f;
    #pragma unroll
    for (int k = 1; k < 8; k++) lpi[k] = lg[k-1];
    float m = lpi[0];
    #pragma unroll
    for (int k = 1; k < 8; k++) m = fmaxf(m, lpi[k]);
    float e[8], se = 0.0f;
    #pragma unroll
    for (int k = 0; k < 8; k++) { e[k] = __expf(lpi[k] - m); se += e[k]; }
    float lse = m + __logf(se);

    float lp = D0.x*(lpi[0]-lse) + D0.y*(lpi[1]-lse) + D0.z*(lpi[2]-lse) + D0.w*(lpi[3]-lse)
             + D1.x*(lpi[4]-lse) + D1.y*(lpi[5]-lse) + D1.z*(lpi[6]-lse) + D1.w*(lpi[7]-lse);
    lp_out += lp * missf;

    float uv[8] = {G0.x,G0.y,G0.z,G0.w,G1.x,G1.y,G1.z,G1.w};
    float t[8];
    #pragma unroll
    for (int k = 0; k < 8; k++) {
        float u = fminf(fmaxf(uv[k], 1e-6f), 1.0f - 1e-6f);
        t[k] = neg_log_u(u);
    }
    float be = e[0], bt = t[0]; int bi = 0;
    #pragma unroll
    for (int k = 1; k < 8; k++) {
        if (e[k]*bt > be*t[k]) { be = e[k]; bt = t[k]; bi = k; }
    }
    samp_out = (float)bi;
}

__global__ __launch_bounds__(NTHREADS, 2)
void hivae_kernel(const float* __restrict__ y,   const float* __restrict__ s,
                  const float* __restrict__ st,  const float* __restrict__ bz,
                  const float* __restrict__ br,  const float* __restrict__ eps,
                  const float* __restrict__ gum, const int* __restrict__ miss,
                  float* __restrict__ out)
{
    extern __shared__ float sm[];
    char* smc = (char*)sm + MISS_BYTE_OFF;
    const int tid = threadIdx.x;
    const int rb  = blockIdx.x * ROWS;
    const int warp = tid >> 5, lane = tid & 31;
    const long B64 = (long)B_TOT*64;

    int R[4];
    R[0] = 2*lane; R[1] = 2*lane + 1; R[2] = 64 + 2*lane; R[3] = 64 + 2*lane + 1;

    // kick off weight chunk 0 copy, then stage activations over it
    issue_chunk(0, sm, tid);

    for (int idx = tid; idx < ROWS*DIN; idx += NTHREADS) {
        int row = idx >> 7, c = idx & 127;
        float v = (c < 64) ? y[(rb+row)*64 + c] : s[(rb+row)*64 + (c-64)];
        sm[YS_OFF + c*PAD + row] = v;
    }
    for (int idx = tid; idx < ROWS*64; idx += NTHREADS) {
        int row = idx >> 6, c = idx & 63;
        smc[c*PAD + row] = (char)miss[(rb+row)*64 + c];
    }
    if (tid < ROWS) sm[LP_OFF + tid] = 0.0f;
    __syncthreads();

    float lp_r[4] = {0.f, 0.f, 0.f, 0.f};
    int g = 0;

    // ========== categorical: 2 passes x 4 chunks of 32 d ===================
    #pragma unroll 1
    for (int jj = 0; jj < 2; jj++) {
        const int fp = jj*8 + warp;
        u64 acc[4][7];
        {
            const float2* bp = &g_bc2[fp*8];
            #pragma unroll
            for (int o = 0; o < 7; o++) {
                float2 b = bp[o];
                u64 v = pack2(b.x, b.y);
                acc[0][o] = v; acc[1][o] = v; acc[2][o] = v; acc[3][o] = v;
            }
        }
        #pragma unroll 1
        for (int c = 0; c < 4; c++, g++) {
            issue_chunk(g+1, sm, tid);
            wait_prev();
            __syncthreads();
            const float* wb = sm + WBUF_OFF + (g&1)*4096 + warp*16;
            const int dbase = c*32;
            #pragma unroll 4
            for (int dd = 0; dd < 32; dd++) {
                const ulonglong2* wp = (const ulonglong2*)(wb + dd*128);
                ulonglong2 w0 = wp[0], w1 = wp[1], w2 = wp[2];
                u64 w6 = *(const u64*)(wp + 3);
                u64 A[4];
                ld_rowpair(&sm[YS_OFF + (dbase+dd)*PAD + 2*lane],      A[0], A[1]);
                ld_rowpair(&sm[YS_OFF + (dbase+dd)*PAD + 64 + 2*lane], A[2], A[3]);
                #pragma unroll
                for (int i = 0; i < 4; i++) {
                    fma2(acc[i][0], A[i], w0.x); fma2(acc[i][1], A[i], w0.y);
                    fma2(acc[i][2], A[i], w1.x); fma2(acc[i][3], A[i], w1.y);
                    fma2(acc[i][4], A[i], w2.x); fma2(acc[i][5], A[i], w2.y);
                    fma2(acc[i][6], A[i], w6);
                }
            }
            __syncthreads();
        }
        // epilogue (overlaps next chunk's in-flight copy)
        #pragma unroll 1
        for (int i = 0; i < 4; i++) {
            const int r = R[i];
            const long grow = rb + r;
            const float4* gup = (const float4*)(gum + grow*256 + fp*16);
            const float4* dcp = (const float4*)(st + grow*288 + 32 + fp*16);
            float4 G0 = gup[0], G1 = gup[1], G2 = gup[2], G3 = gup[3];
            float4 D0 = dcp[0], D1 = dcp[1], D2 = dcp[2], D3 = dcp[3];
            float lg0[7], lg1[7];
            #pragma unroll
            for (int o = 0; o < 7; o++) {
                float2 v = unpack2(acc[i][o]); lg0[o] = v.x; lg1[o] = v.y;
            }
            float s0, s1;
            cat_epilogue(lg0, G0, G1, D0, D1,
                         (float)smc[(32+2*fp)*PAD + r], lp_r[i], s0);
            cat_epilogue(lg1, G2, G3, D2, D3,
                         (float)smc[(33+2*fp)*PAD + r], lp_r[i], s1);
            *(float2*)&out[grow*64 + 32 + 2*fp] = make_float2(s0, s1);
        }
    }

    // ========== mean_pz: 1 chunk (g=8), 8 z x 4 rows =========================
    {
        const int zb = warp*8;
        u64 az[4][4];
        {
            float4 b0 = *(const float4*)&bz[zb];
            float4 b1 = *(const float4*)&bz[zb + 4];
            u64 v0 = pack2(b0.x, b0.y), v1 = pack2(b0.z, b0.w);
            u64 v2 = pack2(b1.x, b1.y), v3 = pack2(b1.z, b1.w);
            #pragma unroll
            for (int i = 0; i < 4; i++) {
                az[i][0] = v0; az[i][1] = v1; az[i][2] = v2; az[i][3] = v3;
            }
        }
        issue_chunk(g+1, sm, tid);
        wait_prev();
        __syncthreads();
        const float* wb = sm + WBUF_OFF + (g&1)*4096 + zb;
        #pragma unroll 4
        for (int dd = 0; dd < SDIM; dd++) {
            ulonglong2 w0 = *(const ulonglong2*)(wb + dd*64);
            ulonglong2 w1 = *(const ulonglong2*)(wb + dd*64 + 4);
            u64 A[4];
            ld_rowpair(&sm[YS_OFF + (64+dd)*PAD + 2*lane],      A[0], A[1]);
            ld_rowpair(&sm[YS_OFF + (64+dd)*PAD + 64 + 2*lane], A[2], A[3]);
            #pragma unroll
            for (int i = 0; i < 4; i++) {
                fma2(az[i][0], A[i], w0.x); fma2(az[i][1], A[i], w0.y);
                fma2(az[i][2], A[i], w1.x); fma2(az[i][3], A[i], w1.y);
            }
        }
        __syncthreads();
        g++;
        #pragma unroll
        for (int i = 0; i < 4; i++) {
            const long grow = rb + R[i];
            float2 p0 = unpack2(az[i][0]), p1 = unpack2(az[i][1]);
            float2 p2 = unpack2(az[i][2]), p3 = unpack2(az[i][3]);
            *(float4*)&out[B64 + grow*64 + zb]     = make_float4(p0.x, p0.y, p1.x, p1.y);
            *(float4*)&out[B64 + grow*64 + zb + 4] = make_float4(p2.x, p2.y, p3.x, p3.y);
        }
    }

    // ========== real GEMV: 2 chunks (g=9,10), 4 features x 4 rows ===========
    u64 ar[4][4];
    const int f0 = warp*4;
    {
        float4 b0 = *(const float4*)&br[f0*2];
        float4 b1 = *(const float4*)&br[f0*2 + 4];
        u64 v0 = pack2(b0.x, b0.y), v1 = pack2(b0.z, b0.w);
        u64 v2 = pack2(b1.x, b1.y), v3 = pack2(b1.z, b1.w);
        #pragma unroll
        for (int i = 0; i < 4; i++) {
            ar[i][0] = v0; ar[i][1] = v1; ar[i][2] = v2; ar[i][3] = v3;
        }
        #pragma unroll 1
        for (int c = 0; c < 2; c++, g++) {
            issue_chunk(g+1, sm, tid);
            wait_prev();
            __syncthreads();
            const float* wb = sm + WBUF_OFF + (g&1)*4096 + f0*2;
            const int dbase = c*64;
            #pragma unroll 4
            for (int dd = 0; dd < 64; dd++) {
                ulonglong2 wA = *(const ulonglong2*)(wb + dd*64);
                ulonglong2 wB = *(const ulonglong2*)(wb + dd*64 + 4);
                u64 A[4];
                ld_rowpair(&sm[YS_OFF + (dbase+dd)*PAD + 2*lane],      A[0], A[1]);
                ld_rowpair(&sm[YS_OFF + (dbase+dd)*PAD + 64 + 2*lane], A[2], A[3]);
                #pragma unroll
                for (int i = 0; i < 4; i++) {
                    fma2(ar[i][0], A[i], wA.x); fma2(ar[i][1], A[i], wA.y);
                    fma2(ar[i][2], A[i], wB.x); fma2(ar[i][3], A[i], wB.y);
                }
            }
            __syncthreads();
        }
    }

    // ---- all YS reads done: overlay st/eps into the YS region -------------
    for (int idx = tid; idx < ROWS*32; idx += NTHREADS) {
        int row = idx >> 5, c = idx & 31;
        sm[ST2_OFF  + c*PAD + row] = st[(rb+row)*288 + c];
        sm[EPS2_OFF + c*PAD + row] = eps[(rb+row)*32 + c];
    }
    __syncthreads();

    // ========== real epilogue ==============================================
    {
        #pragma unroll 1
        for (int i = 0; i < 4; i++) {
            const int r = R[i];
            const long grow = rb + r;
            float samp[4];
            #pragma unroll
            for (int qf = 0; qf < 4; qf++) {
                const int f = f0 + qf;
                float2 mv = unpack2(ar[i][qf]);
                float mu = mv.x;
                float lv = fminf(fmaxf(mv.y, -10.0f), 10.0f);
                float x  = sm[ST2_OFF + f*PAD + r];
                float mi = (float)smc[f*PAD + r];
                float dmu = x - mu;
                lp_r[i] += (-0.5f*dmu*dmu*__expf(-lv) - 0.5f*lv - HALF_LOG2PI) * mi;
                float sd = fmaxf(__expf(0.5f*lv), 1e-6f);
                samp[qf] = mu + sd * sm[EPS2_OFF + f*PAD + r];
            }
            *(float4*)&out[grow*64 + f0] = make_float4(samp[0], samp[1], samp[2], samp[3]);
        }
    }

    // -------- log-p reduction + zeros ---------------------------------------
    #pragma unroll
    for (int i = 0; i < 4; i++)
        atomicAdd(&sm[LP_OFF + R[i]], lp_r[i]);

    {
        const float4 z4 = make_float4(0.f,0.f,0.f,0.f);
        for (int idx = tid; idx < ROWS*16; idx += NTHREADS) {
            int row = idx >> 4, c = (idx & 15)*4;
            *(float4*)&out[2*B64 + (long)(rb+row)*64 + c] = z4;
        }
    }

    __syncthreads();
    if (tid < ROWS) out[3*B64 + rb + tid] = sm[LP_OFF + tid];
}

extern "C" void kernel_launch(void* const* d_in, const int* in_sizes, int n_in,
                              void* d_out, int out_size)
{
    const float* y    = (const float*)d_in[0];
    const float* s    = (const float*)d_in[1];
    const float* st   = (const float*)d_in[2];
    const float* Wz   = (const float*)d_in[3];
    const float* bz   = (const float*)d_in[4];
    const float* Wr   = (const float*)d_in[5];
    const float* br   = (const float*)d_in[6];
    const float* Wc   = (const float*)d_in[7];
    const float* bc   = (const float*)d_in[8];
    const float* eps  = (const float*)d_in[9];
    const float* gum  = (const float*)d_in[10];
    const int*   miss = (const int*)d_in[11];
    float* out = (float*)d_out;

    cudaFuncSetAttribute(hivae_kernel,
                         cudaFuncAttributeMaxDynamicSharedMemorySize, SMEM_BYTES);
    repack_kernel<<<16, 256>>>(Wc, Wr, Wz, bc);
    hivae_kernel<<<B_TOT/ROWS, NTHREADS, SMEM_BYTES>>>(
        y, s, st, bz, br, eps, gum, miss, out);
}